// round 5
// baseline (speedup 1.0000x reference)
#include <cuda_runtime.h>
#include <cuda_fp16.h>
#include <math.h>
#include <stdint.h>

#define NN 50000
#define EE 800000
#define DIN 128
#define DH 64
#define DOUT 16
#define NCHUNK ((NN + 255) / 256)   // 196
#define GRID 296                    // 2 blocks x 148 SMs (GB300 has 152; still resident)
#define NBAR 9

// Scratch (device globals; no allocation allowed)
__device__ __align__(256) __half g_th[NN * DH];      // GEMM out / agg in
__device__ __align__(256) __half g_ha[NN * DH];      // agg out / GEMM in / fc in
__device__ __align__(256) __half g_w0h[DIN * DH];
__device__ __align__(256) __half g_w1h[DH * DH];
__device__ __align__(256) __half g_w2h[DH * DH];
__device__ float g_dinv[NN];
__device__ int g_cnt[NN];
__device__ int g_lexcl[NN];
__device__ int g_rowptr[NN + 1];
__device__ int g_loc[EE];
__device__ int g_col[EE];
__device__ int g_chtot[256];
__device__ int g_bar[NBAR];   // zero-init; restored to zero at end of each launch
__device__ int g_exit;        // exit rendezvous counter

// ---------------------------------------------------------------- grid barrier
__device__ __forceinline__ void grid_bar(int idx) {
    __syncthreads();
    if (threadIdx.x == 0) {
        __threadfence();
        int old = atomicAdd(&g_bar[idx], 1);
        if (old + 1 < (int)gridDim.x) {
            while (*(volatile int*)&g_bar[idx] < (int)gridDim.x) __nanosleep(64);
        }
        __threadfence();
    }
    __syncthreads();
}

// ---------------------------------------------------------------- mma helper
__device__ __forceinline__ void mma16816(float* d, uint32_t a0, uint32_t a1,
                                         uint32_t a2, uint32_t a3, uint32_t b0,
                                         uint32_t b1) {
    asm volatile(
        "mma.sync.aligned.m16n8k16.row.col.f32.f16.f16.f32 "
        "{%0,%1,%2,%3}, {%4,%5,%6,%7}, {%8,%9}, {%0,%1,%2,%3};\n"
        : "+f"(d[0]), "+f"(d[1]), "+f"(d[2]), "+f"(d[3])
        : "r"(a0), "r"(a1), "r"(a2), "r"(a3), "r"(b0), "r"(b1));
}

// shared compute for a 128x64 tile given sA (LDA halves/row) + sB (64 x LDB)
template <int K, int LDA, int LDB>
__device__ __forceinline__ void gemm_tile_compute(const __half* sA, const __half* sB,
                                                  __half* C, int base) {
    int tid = threadIdx.x;
    int warp = tid >> 5, lane = tid & 31;
    int grp = lane >> 2, tig = lane & 3;
    int rowA = warp * 16 + grp;
    float acc[8][4];
#pragma unroll
    for (int j = 0; j < 8; j++)
#pragma unroll
        for (int q = 0; q < 4; q++) acc[j][q] = 0.f;

#pragma unroll
    for (int kc = 0; kc < K; kc += 16) {
        uint32_t a0 = *(const uint32_t*)(sA + rowA * LDA + kc + 2 * tig);
        uint32_t a1 = *(const uint32_t*)(sA + (rowA + 8) * LDA + kc + 2 * tig);
        uint32_t a2 = *(const uint32_t*)(sA + rowA * LDA + kc + 2 * tig + 8);
        uint32_t a3 = *(const uint32_t*)(sA + (rowA + 8) * LDA + kc + 2 * tig + 8);
#pragma unroll
        for (int j = 0; j < 8; j++) {
            uint32_t b0 = *(const uint32_t*)(sB + (j * 8 + grp) * LDB + kc + 2 * tig);
            uint32_t b1 = *(const uint32_t*)(sB + (j * 8 + grp) * LDB + kc + 2 * tig + 8);
            mma16816(acc[j], a0, a1, a2, a3, b0, b1);
        }
    }
    int r0 = base + rowA, r1 = r0 + 8;
#pragma unroll
    for (int j = 0; j < 8; j++) {
        int col = j * 8 + 2 * tig;
        if (r0 < NN)
            *(__half2*)(C + (size_t)r0 * DH + col) = __floats2half2_rn(acc[j][0], acc[j][1]);
        if (r1 < NN)
            *(__half2*)(C + (size_t)r1 * DH + col) = __floats2half2_rn(acc[j][2], acc[j][3]);
    }
}

// GEMM0: A fp32 [N,128], W fp16 (pre-converted), C fp16
__device__ void gemm0_phase(const float* __restrict__ A, __half* smdyn,
                            __half* __restrict__ C) {
    constexpr int K = DIN, LDA = K + 8, LDB = K + 8;
    __half* sA = smdyn;
    __half* sB = smdyn + 128 * LDA;
    int tid = threadIdx.x;
    for (int i = tid; i < K * 64; i += 256) {
        int k = i >> 6, n = i & 63;
        sB[n * LDB + k] = g_w0h[i];
    }
    __syncthreads();
    const int ntiles = (NN + 127) / 128;
    for (int tile = blockIdx.x; tile < ntiles; tile += gridDim.x) {
        int base = tile * 128;
        for (int i = tid; i < 128 * (K / 4); i += 256) {
            int r = i / (K / 4), c = i % (K / 4);
            float4 v = make_float4(0.f, 0.f, 0.f, 0.f);
            if (base + r < NN) v = *(const float4*)(A + (size_t)(base + r) * K + c * 4);
            __half2* p = (__half2*)(sA + r * LDA + c * 4);
            p[0] = __floats2half2_rn(v.x, v.y);
            p[1] = __floats2half2_rn(v.z, v.w);
        }
        __syncthreads();
        gemm_tile_compute<K, LDA, LDB>(sA, sB, C, base);
        __syncthreads();
    }
}

// GEMM 1/2: A fp16 [N,64]
__device__ void gemm64_phase(const __half* __restrict__ A, const __half* __restrict__ W,
                             __half* smdyn, __half* __restrict__ C) {
    constexpr int K = DH, LDA = K + 8, LDB = K + 8;
    __half* sA = smdyn;
    __half* sB = smdyn + 128 * LDA;
    int tid = threadIdx.x;
    for (int i = tid; i < K * 64; i += 256) {
        int k = i >> 6, n = i & 63;
        sB[n * LDB + k] = W[i];
    }
    __syncthreads();
    const int ntiles = (NN + 127) / 128;
    for (int tile = blockIdx.x; tile < ntiles; tile += gridDim.x) {
        int base = tile * 128;
        for (int i = tid; i < 128 * (K / 8); i += 256) {
            int r = i / (K / 8), c = i % (K / 8);
            uint4 v = make_uint4(0u, 0u, 0u, 0u);
            if (base + r < NN) v = *(const uint4*)(A + (size_t)(base + r) * K + c * 8);
            *(uint4*)(sA + r * LDA + c * 8) = v;
        }
        __syncthreads();
        gemm_tile_compute<K, LDA, LDB>(sA, sB, C, base);
        __syncthreads();
    }
}

// ---------------------------------------------------------------- scan pieces
__device__ void scan1_block(int b) {
    __shared__ int wsum[8];
    int tid = threadIdx.x;
    int i = b * 256 + tid;
    int v = (i < NN) ? g_cnt[i] : 0;
    if (i < NN) g_dinv[i] = rsqrtf((float)(v + 1));
    int lane = tid & 31, w = tid >> 5;
    int incl = v;
#pragma unroll
    for (int o = 1; o < 32; o <<= 1) {
        int t = __shfl_up_sync(0xffffffffu, incl, o);
        if (lane >= o) incl += t;
    }
    if (lane == 31) wsum[w] = incl;
    __syncthreads();
    if (w == 0) {
        int s = (lane < 8) ? wsum[lane] : 0;
#pragma unroll
        for (int o = 1; o < 8; o <<= 1) {
            int t = __shfl_up_sync(0xffffffffu, s, o);
            if (lane >= o) s += t;
        }
        if (lane < 8) wsum[lane] = s;
    }
    __syncthreads();
    int woff = (w > 0) ? wsum[w - 1] : 0;
    if (i < NN) g_lexcl[i] = woff + incl - v;
    if (tid == 255) g_chtot[b] = woff + incl;
    __syncthreads();
}

__device__ void finish_phase(const int* __restrict__ src, const int* __restrict__ dst) {
    __shared__ int soff[256];
    __shared__ int wsum[8];
    int tid = threadIdx.x;
    {   // per-block redundant scan of chunk totals
        int v = (tid < NCHUNK) ? g_chtot[tid] : 0;
        int lane = tid & 31, w = tid >> 5;
        int incl = v;
#pragma unroll
        for (int o = 1; o < 32; o <<= 1) {
            int t = __shfl_up_sync(0xffffffffu, incl, o);
            if (lane >= o) incl += t;
        }
        if (lane == 31) wsum[w] = incl;
        __syncthreads();
        if (w == 0) {
            int s = (lane < 8) ? wsum[lane] : 0;
#pragma unroll
            for (int o = 1; o < 8; o <<= 1) {
                int t = __shfl_up_sync(0xffffffffu, s, o);
                if (lane >= o) s += t;
            }
            if (lane < 8) wsum[lane] = s;
        }
        __syncthreads();
        int woff = (w > 0) ? wsum[w - 1] : 0;
        soff[tid] = woff + incl - v;
        __syncthreads();
    }
    const int EBLKS = (EE + 255) / 256;
    for (int b = blockIdx.x; b < NCHUNK + EBLKS; b += gridDim.x) {
        if (b < NCHUNK) {
            int i = b * 256 + tid;
            if (i < NN) g_rowptr[i] = g_lexcl[i] + soff[b];
            if (b == 0 && tid == 0) g_rowptr[NN] = EE;
        } else {
            int i = (b - NCHUNK) * 256 + tid;
            if (i < EE) {
                int d = dst[i];
                g_col[g_lexcl[d] + soff[d >> 8] + g_loc[i]] = src[i];
            }
        }
    }
}

// ---------------------------------------------------------------- aggregation
__device__ void agg_phase(const __half2* __restrict__ hin, __half2* __restrict__ hout,
                          const float* __restrict__ bias) {
    int lane = threadIdx.x & 31;
    int sub = threadIdx.x >> 5;  // 0..7
    float2 bb = ((const float2*)bias)[lane];
    const int ngrp = (NN + 7) / 8;
    for (int g = blockIdx.x; g < ngrp; g += gridDim.x) {
        int node = g * 8 + sub;
        if (node >= NN) continue;
        float dd = g_dinv[node];
        int beg = g_rowptr[node], end = g_rowptr[node + 1];
        float2 hv = __half22float2(hin[(size_t)node * 32 + lane]);
        float2 acc = make_float2(hv.x * dd * dd, hv.y * dd * dd);
        int k = beg;
        for (; k + 4 <= end; k += 4) {
            int j0 = g_col[k], j1 = g_col[k + 1], j2 = g_col[k + 2], j3 = g_col[k + 3];
            float n0 = g_dinv[j0] * dd, n1 = g_dinv[j1] * dd;
            float n2 = g_dinv[j2] * dd, n3 = g_dinv[j3] * dd;
            float2 h0 = __half22float2(hin[(size_t)j0 * 32 + lane]);
            float2 h1 = __half22float2(hin[(size_t)j1 * 32 + lane]);
            float2 h2 = __half22float2(hin[(size_t)j2 * 32 + lane]);
            float2 h3 = __half22float2(hin[(size_t)j3 * 32 + lane]);
            acc.x = fmaf(h0.x, n0, acc.x); acc.y = fmaf(h0.y, n0, acc.y);
            acc.x = fmaf(h1.x, n1, acc.x); acc.y = fmaf(h1.y, n1, acc.y);
            acc.x = fmaf(h2.x, n2, acc.x); acc.y = fmaf(h2.y, n2, acc.y);
            acc.x = fmaf(h3.x, n3, acc.x); acc.y = fmaf(h3.y, n3, acc.y);
        }
        for (; k < end; k++) {
            int j = g_col[k];
            float n = g_dinv[j] * dd;
            float2 h = __half22float2(hin[(size_t)j * 32 + lane]);
            acc.x = fmaf(h.x, n, acc.x);
            acc.y = fmaf(h.y, n, acc.y);
        }
        acc.x += bb.x;
        acc.y += bb.y;
        acc.x = (acc.x > 0.f) ? acc.x : expm1f(acc.x);
        acc.y = (acc.y > 0.f) ? acc.y : expm1f(acc.y);
        hout[(size_t)node * 32 + lane] = __floats2half2_rn(acc.x, acc.y);
    }
}

// ---------------------------------------------------------------- FC + softmax
__device__ void fc_phase(const __half2* __restrict__ h, const float* __restrict__ fw,
                         const float* __restrict__ fb, float* __restrict__ out) {
    __shared__ float sW[DH * DOUT];
    __shared__ float sh[8][DH];
    for (int i = threadIdx.x; i < DH * DOUT; i += 256) sW[i] = fw[i];
    __syncthreads();
    int warp = threadIdx.x >> 5, lane = threadIdx.x & 31;
    const int ngrp = (NN + 7) / 8;
    for (int g = blockIdx.x; g < ngrp; g += gridDim.x) {
        int node = g * 8 + warp;
        if (node >= NN) continue;
        float2 hv = __half22float2(h[(size_t)node * 32 + lane]);
        sh[warp][2 * lane] = hv.x;
        sh[warp][2 * lane + 1] = hv.y;
        __syncwarp();
        float v = 0.f;
        if (lane < DOUT) {
            v = fb[lane];
#pragma unroll
            for (int kk = 0; kk < DH; kk++) v = fmaf(sh[warp][kk], sW[kk * DOUT + lane], v);
        }
        float m = v;
#pragma unroll
        for (int o = 8; o; o >>= 1) m = fmaxf(m, __shfl_xor_sync(0xffffffffu, m, o, 16));
        float e = (lane < DOUT) ? expf(v - m) : 0.f;
        float s = e;
#pragma unroll
        for (int o = 8; o; o >>= 1) s += __shfl_xor_sync(0xffffffffu, s, o, 16);
        if (lane < DOUT) out[(size_t)node * DOUT + lane] = e / s;
        __syncwarp();
    }
}

// ---------------------------------------------------------------- fused kernel
__global__ void __launch_bounds__(256, 2)
k_fused(const float* __restrict__ x, const int* __restrict__ src,
        const int* __restrict__ dst, const float* __restrict__ w0,
        const float* __restrict__ b0, const float* __restrict__ w1,
        const float* __restrict__ b1, const float* __restrict__ w2,
        const float* __restrict__ b2, const float* __restrict__ fw,
        const float* __restrict__ fb, float* __restrict__ out) {
    extern __shared__ __half smdyn[];
    int gtid = blockIdx.x * 256 + threadIdx.x;
    int gstride = gridDim.x * 256;

    // P0: zero degree counts + convert weights to fp16
    for (int i = gtid; i < NN; i += gstride) g_cnt[i] = 0;
    for (int i = gtid; i < DIN * DH; i += gstride) {
        g_w0h[i] = __float2half_rn(w0[i]);
        if (i < DH * DH) {
            g_w1h[i] = __float2half_rn(w1[i]);
            g_w2h[i] = __float2half_rn(w2[i]);
        }
    }
    grid_bar(0);

    // P1: degree count (+ per-edge slot) and GEMM0 (independent work)
    for (int i = gtid; i < EE; i += gstride) g_loc[i] = atomicAdd(&g_cnt[dst[i]], 1);
    gemm0_phase(x, smdyn, g_th);
    grid_bar(1);

    // P2: chunk-local scan + dinv
    for (int b = blockIdx.x; b < NCHUNK; b += gridDim.x) scan1_block(b);
    grid_bar(2);

    // P3: rowptr finalize + CSR scatter
    finish_phase(src, dst);
    grid_bar(3);

    // P4..P8: agg / gemm / agg / gemm / agg
    agg_phase((const __half2*)g_th, (__half2*)g_ha, b0);
    grid_bar(4);
    gemm64_phase(g_ha, g_w1h, smdyn, g_th);
    grid_bar(5);
    agg_phase((const __half2*)g_th, (__half2*)g_ha, b1);
    grid_bar(6);
    gemm64_phase(g_ha, g_w2h, smdyn, g_th);
    grid_bar(7);
    agg_phase((const __half2*)g_th, (__half2*)g_ha, b2);
    grid_bar(8);

    // P9: FC + softmax
    fc_phase((const __half2*)g_ha, fw, fb, out);

    // exit rendezvous + barrier reset for next graph replay
    __syncthreads();
    if (threadIdx.x == 0) {
        __threadfence();
        atomicAdd(&g_exit, 1);
        if (blockIdx.x == 0) {
            while (*(volatile int*)&g_exit < (int)gridDim.x) __nanosleep(64);
            for (int i = 0; i < NBAR; i++) g_bar[i] = 0;
            __threadfence();
            g_exit = 0;
            __threadfence();
        }
    }
}

// ---------------------------------------------------------------- launch
extern "C" void kernel_launch(void* const* d_in, const int* in_sizes, int n_in,
                              void* d_out, int out_size) {
    const float* x = (const float*)d_in[0];
    const int* ei = (const int*)d_in[1];
    const float* w0 = (const float*)d_in[2];
    const float* b0 = (const float*)d_in[3];
    const float* w1 = (const float*)d_in[4];
    const float* b1 = (const float*)d_in[5];
    const float* w2 = (const float*)d_in[6];
    const float* b2 = (const float*)d_in[7];
    const float* fw = (const float*)d_in[8];
    const float* fb = (const float*)d_in[9];
    float* out = (float*)d_out;
    const int* src = ei;
    const int* dst = ei + EE;

    const int smem = (128 * (DIN + 8) + 64 * (DIN + 8)) * 2;  // 52224 B
    static int configured = 0;
    cudaFuncSetAttribute(k_fused, cudaFuncAttributeMaxDynamicSharedMemorySize, smem);
    (void)configured;

    k_fused<<<GRID, 256, smem>>>(x, src, dst, w0, b0, w1, b1, w2, b2, fw, fb, out);
}

// round 6
// speedup vs baseline: 1.6628x; 1.6628x over previous
#include <cuda_runtime.h>
#include <cuda_fp16.h>
#include <math.h>
#include <stdint.h>

#define NN 50000
#define EE 800000
#define DIN 128
#define DH 64
#define DOUT 16
#define NCHUNK ((NN + 255) / 256)   // 196
#define EBLK ((EE + 255) / 256)     // 3125

// Scratch (device globals; no allocation allowed)
__device__ __align__(256) __half g_th[NN * DH];      // GEMM out / agg in
__device__ __align__(256) __half g_ha[NN * DH];      // agg out / GEMM in
__device__ __align__(256) __half g_w0h[DIN * DH];
__device__ __align__(256) __half g_w1h[DH * DH];
__device__ __align__(256) __half g_w2h[DH * DH];
__device__ float g_dinv[NN];
__device__ int g_cnt[NN];
__device__ int g_lexcl[NN];
__device__ int g_rowptr[NN + 1];
__device__ int g_loc[EE];
__device__ int g_col[EE];
__device__ int g_chtot[256];

// ---------------------------------------------------------------- prep: zero cnt + cvt weights
__global__ void k_prep(const float* __restrict__ w0, const float* __restrict__ w1,
                       const float* __restrict__ w2) {
    int i = blockIdx.x * 256 + threadIdx.x;
    if (i < NN) g_cnt[i] = 0;
    if (i < DIN * DH) g_w0h[i] = __float2half_rn(w0[i]);
    if (i < DH * DH) {
        g_w1h[i] = __float2half_rn(w1[i]);
        g_w2h[i] = __float2half_rn(w2[i]);
    }
}

// ---------------------------------------------------------------- preprocessing
__global__ void k_count(const int* __restrict__ dst) {
    int i = blockIdx.x * blockDim.x + threadIdx.x;
    if (i < EE) g_loc[i] = atomicAdd(&g_cnt[dst[i]], 1);
}

__global__ void k_scan1() {
    __shared__ int wsum[8];
    int tid = threadIdx.x;
    int i = blockIdx.x * 256 + tid;
    int v = (i < NN) ? g_cnt[i] : 0;
    if (i < NN) g_dinv[i] = rsqrtf((float)(v + 1));
    int lane = tid & 31, w = tid >> 5;
    int incl = v;
#pragma unroll
    for (int o = 1; o < 32; o <<= 1) {
        int t = __shfl_up_sync(0xffffffffu, incl, o);
        if (lane >= o) incl += t;
    }
    if (lane == 31) wsum[w] = incl;
    __syncthreads();
    if (w == 0) {
        int s = (lane < 8) ? wsum[lane] : 0;
#pragma unroll
        for (int o = 1; o < 8; o <<= 1) {
            int t = __shfl_up_sync(0xffffffffu, s, o);
            if (lane >= o) s += t;
        }
        if (lane < 8) wsum[lane] = s;
    }
    __syncthreads();
    int woff = (w > 0) ? wsum[w - 1] : 0;
    if (i < NN) g_lexcl[i] = woff + incl - v;
    if (tid == 255) g_chtot[blockIdx.x] = woff + incl;
}

__global__ void k_finish(const int* __restrict__ src, const int* __restrict__ dst) {
    __shared__ int soff[256];
    __shared__ int wsum[8];
    int tid = threadIdx.x;
    {
        int v = (tid < NCHUNK) ? g_chtot[tid] : 0;
        int lane = tid & 31, w = tid >> 5;
        int incl = v;
#pragma unroll
        for (int o = 1; o < 32; o <<= 1) {
            int t = __shfl_up_sync(0xffffffffu, incl, o);
            if (lane >= o) incl += t;
        }
        if (lane == 31) wsum[w] = incl;
        __syncthreads();
        if (w == 0) {
            int s = (lane < 8) ? wsum[lane] : 0;
#pragma unroll
            for (int o = 1; o < 8; o <<= 1) {
                int t = __shfl_up_sync(0xffffffffu, s, o);
                if (lane >= o) s += t;
            }
            if (lane < 8) wsum[lane] = s;
        }
        __syncthreads();
        int woff = (w > 0) ? wsum[w - 1] : 0;
        soff[tid] = woff + incl - v;
        __syncthreads();
    }
    int b = blockIdx.x;
    if (b < NCHUNK) {
        int i = b * 256 + tid;
        if (i < NN) g_rowptr[i] = g_lexcl[i] + soff[b];
        if (b == 0 && tid == 0) g_rowptr[NN] = EE;
    } else {
        int i = (b - NCHUNK) * 256 + tid;
        if (i < EE) {
            int d = dst[i];
            g_col[g_lexcl[d] + soff[d >> 8] + g_loc[i]] = src[i];
        }
    }
}

// ---------------------------------------------------------------- tensor-core GEMM
__device__ __forceinline__ void mma16816(float* d, uint32_t a0, uint32_t a1,
                                         uint32_t a2, uint32_t a3, uint32_t b0,
                                         uint32_t b1) {
    asm volatile(
        "mma.sync.aligned.m16n8k16.row.col.f32.f16.f16.f32 "
        "{%0,%1,%2,%3}, {%4,%5,%6,%7}, {%8,%9}, {%0,%1,%2,%3};\n"
        : "+f"(d[0]), "+f"(d[1]), "+f"(d[2]), "+f"(d[3])
        : "r"(a0), "r"(a1), "r"(a2), "r"(a3), "r"(b0), "r"(b1));
}

template <int K, int LDA, int LDB>
__device__ __forceinline__ void gemm_tile_compute(const __half* sA, const __half* sB,
                                                  __half* C, int base) {
    int tid = threadIdx.x;
    int warp = tid >> 5, lane = tid & 31;
    int grp = lane >> 2, tig = lane & 3;
    int rowA = warp * 16 + grp;
    float acc[8][4];
#pragma unroll
    for (int j = 0; j < 8; j++)
#pragma unroll
        for (int q = 0; q < 4; q++) acc[j][q] = 0.f;

#pragma unroll
    for (int kc = 0; kc < K; kc += 16) {
        uint32_t a0 = *(const uint32_t*)(sA + rowA * LDA + kc + 2 * tig);
        uint32_t a1 = *(const uint32_t*)(sA + (rowA + 8) * LDA + kc + 2 * tig);
        uint32_t a2 = *(const uint32_t*)(sA + rowA * LDA + kc + 2 * tig + 8);
        uint32_t a3 = *(const uint32_t*)(sA + (rowA + 8) * LDA + kc + 2 * tig + 8);
#pragma unroll
        for (int j = 0; j < 8; j++) {
            uint32_t b0 = *(const uint32_t*)(sB + (j * 8 + grp) * LDB + kc + 2 * tig);
            uint32_t b1 = *(const uint32_t*)(sB + (j * 8 + grp) * LDB + kc + 2 * tig + 8);
            mma16816(acc[j], a0, a1, a2, a3, b0, b1);
        }
    }
    int r0 = base + rowA, r1 = r0 + 8;
#pragma unroll
    for (int j = 0; j < 8; j++) {
        int col = j * 8 + 2 * tig;
        if (r0 < NN)
            *(__half2*)(C + (size_t)r0 * DH + col) = __floats2half2_rn(acc[j][0], acc[j][1]);
        if (r1 < NN)
            *(__half2*)(C + (size_t)r1 * DH + col) = __floats2half2_rn(acc[j][2], acc[j][3]);
    }
}

// GEMM0: reads fp32 x directly, converts in smem stage
__global__ void k_gemm0(const float* __restrict__ A, __half* __restrict__ C) {
    constexpr int K = DIN, LDA = K + 8, LDB = K + 8;
    extern __shared__ __half sm[];
    __half* sA = sm;
    __half* sB = sm + 128 * LDA;
    int tid = threadIdx.x;
    int base = blockIdx.x * 128;

    for (int i = tid; i < K * 64; i += 256) {
        int k = i >> 6, n = i & 63;
        sB[n * LDB + k] = g_w0h[i];
    }
    for (int i = tid; i < 128 * (K / 4); i += 256) {
        int r = i / (K / 4), c = i % (K / 4);
        float4 v = make_float4(0.f, 0.f, 0.f, 0.f);
        if (base + r < NN) v = *(const float4*)(A + (size_t)(base + r) * K + c * 4);
        __half2* p = (__half2*)(sA + r * LDA + c * 4);
        p[0] = __floats2half2_rn(v.x, v.y);
        p[1] = __floats2half2_rn(v.z, v.w);
    }
    __syncthreads();
    gemm_tile_compute<K, LDA, LDB>(sA, sB, C, base);
}

// GEMM 1/2: fp16 in
__global__ void k_gemm64(const __half* __restrict__ A, const __half* __restrict__ W,
                         __half* __restrict__ C) {
    constexpr int K = DH, LDA = K + 8, LDB = K + 8;
    extern __shared__ __half sm[];
    __half* sA = sm;
    __half* sB = sm + 128 * LDA;
    int tid = threadIdx.x;
    int base = blockIdx.x * 128;

    for (int i = tid; i < K * 64; i += 256) {
        int k = i >> 6, n = i & 63;
        sB[n * LDB + k] = W[i];
    }
    for (int i = tid; i < 128 * (K / 8); i += 256) {
        int r = i / (K / 8), c = i % (K / 8);
        uint4 v = make_uint4(0u, 0u, 0u, 0u);
        if (base + r < NN) v = *(const uint4*)(A + (size_t)(base + r) * K + c * 8);
        *(uint4*)(sA + r * LDA + c * 8) = v;
    }
    __syncthreads();
    gemm_tile_compute<K, LDA, LDB>(sA, sB, C, base);
}

// ------------------------------------------------------- aggregation body
__device__ __forceinline__ float2 agg_node(const __half2* __restrict__ hin, int node,
                                           int lane, float2 bb) {
    float dd = g_dinv[node];
    int beg = g_rowptr[node], end = g_rowptr[node + 1];
    float2 hv = __half22float2(hin[(size_t)node * 32 + lane]);
    float2 acc = make_float2(hv.x * dd * dd, hv.y * dd * dd);
    int k = beg;
    for (; k + 4 <= end; k += 4) {
        int j0 = g_col[k], j1 = g_col[k + 1], j2 = g_col[k + 2], j3 = g_col[k + 3];
        float n0 = g_dinv[j0] * dd, n1 = g_dinv[j1] * dd;
        float n2 = g_dinv[j2] * dd, n3 = g_dinv[j3] * dd;
        float2 h0 = __half22float2(hin[(size_t)j0 * 32 + lane]);
        float2 h1 = __half22float2(hin[(size_t)j1 * 32 + lane]);
        float2 h2 = __half22float2(hin[(size_t)j2 * 32 + lane]);
        float2 h3 = __half22float2(hin[(size_t)j3 * 32 + lane]);
        acc.x = fmaf(h0.x, n0, acc.x); acc.y = fmaf(h0.y, n0, acc.y);
        acc.x = fmaf(h1.x, n1, acc.x); acc.y = fmaf(h1.y, n1, acc.y);
        acc.x = fmaf(h2.x, n2, acc.x); acc.y = fmaf(h2.y, n2, acc.y);
        acc.x = fmaf(h3.x, n3, acc.x); acc.y = fmaf(h3.y, n3, acc.y);
    }
    for (; k < end; k++) {
        int j = g_col[k];
        float n = g_dinv[j] * dd;
        float2 h = __half22float2(hin[(size_t)j * 32 + lane]);
        acc.x = fmaf(h.x, n, acc.x);
        acc.y = fmaf(h.y, n, acc.y);
    }
    acc.x += bb.x;
    acc.y += bb.y;
    acc.x = (acc.x > 0.f) ? acc.x : expm1f(acc.x);
    acc.y = (acc.y > 0.f) ? acc.y : expm1f(acc.y);
    return acc;
}

// aggregation + bias + ELU (layers 0,1)
__global__ void k_agg(const __half2* __restrict__ hin, __half2* __restrict__ hout,
                      const float* __restrict__ bias) {
    int lane = threadIdx.x;
    int node = blockIdx.x * 8 + threadIdx.y;
    if (node >= NN) return;
    float2 bb = ((const float2*)bias)[lane];
    float2 acc = agg_node(hin, node, lane, bb);
    hout[(size_t)node * 32 + lane] = __floats2half2_rn(acc.x, acc.y);
}

// last aggregation + FC + softmax fused (layer 2)
__global__ void k_agg_fc(const __half2* __restrict__ hin, const float* __restrict__ bias,
                         const float* __restrict__ fw, const float* __restrict__ fb,
                         float* __restrict__ out) {
    __shared__ float sW[DH * DOUT];
    __shared__ float sh[8][DH];
    for (int i = threadIdx.x; i < DH * DOUT; i += 256) sW[i] = fw[i];
    __syncthreads();
    int warp = threadIdx.x >> 5, lane = threadIdx.x & 31;
    int node = blockIdx.x * 8 + warp;
    if (node >= NN) return;
    float2 bb = ((const float2*)bias)[lane];
    float2 acc = agg_node(hin, node, lane, bb);
    sh[warp][2 * lane] = acc.x;
    sh[warp][2 * lane + 1] = acc.y;
    __syncwarp();
    float v = 0.f;
    if (lane < DOUT) {
        v = fb[lane];
#pragma unroll
        for (int kk = 0; kk < DH; kk++) v = fmaf(sh[warp][kk], sW[kk * DOUT + lane], v);
    }
    float m = v;
#pragma unroll
    for (int o = 8; o; o >>= 1) m = fmaxf(m, __shfl_xor_sync(0xffffffffu, m, o, 16));
    float e = (lane < DOUT) ? expf(v - m) : 0.f;
    float s = e;
#pragma unroll
    for (int o = 8; o; o >>= 1) s += __shfl_xor_sync(0xffffffffu, s, o, 16);
    if (lane < DOUT) out[(size_t)node * DOUT + lane] = e / s;
}

// ---------------------------------------------------------------- launch
extern "C" void kernel_launch(void* const* d_in, const int* in_sizes, int n_in,
                              void* d_out, int out_size) {
    const float* x = (const float*)d_in[0];
    const int* ei = (const int*)d_in[1];
    const float* w0 = (const float*)d_in[2];
    const float* b0 = (const float*)d_in[3];
    const float* w1 = (const float*)d_in[4];
    const float* b1 = (const float*)d_in[5];
    const float* w2 = (const float*)d_in[6];
    const float* b2 = (const float*)d_in[7];
    const float* fw = (const float*)d_in[8];
    const float* fb = (const float*)d_in[9];
    float* out = (float*)d_out;
    const int* src = ei;
    const int* dst = ei + EE;

    __half *p_t, *p_ha, *p_w1, *p_w2;
    cudaGetSymbolAddress((void**)&p_t, g_th);
    cudaGetSymbolAddress((void**)&p_ha, g_ha);
    cudaGetSymbolAddress((void**)&p_w1, g_w1h);
    cudaGetSymbolAddress((void**)&p_w2, g_w2h);

    const int smem128 = (128 * (DIN + 8) + 64 * (DIN + 8)) * 2;  // 52224 B
    const int smem64 = (128 * (DH + 8) + 64 * (DH + 8)) * 2;     // 27648 B
    cudaFuncSetAttribute(k_gemm0, cudaFuncAttributeMaxDynamicSharedMemorySize, smem128);
    cudaFuncSetAttribute(k_gemm64, cudaFuncAttributeMaxDynamicSharedMemorySize, smem64);

    const int gemm_grid = (NN + 127) / 128;
    const dim3 agg_block(32, 8);
    const int agg_grid = (NN + 7) / 8;

    // preprocessing (4 nodes)
    k_prep<<<NCHUNK, 256>>>(w0, w1, w2);
    k_count<<<EBLK, 256>>>(dst);
    k_scan1<<<NCHUNK, 256>>>();
    k_finish<<<NCHUNK + EBLK, 256>>>(src, dst);

    // layers (6 nodes)
    k_gemm0<<<gemm_grid, 256, smem128>>>(x, p_t);
    k_agg<<<agg_grid, agg_block>>>((const __half2*)p_t, (__half2*)p_ha, b0);
    k_gemm64<<<gemm_grid, 256, smem64>>>(p_ha, p_w1, p_t);
    k_agg<<<agg_grid, agg_block>>>((const __half2*)p_t, (__half2*)p_ha, b1);
    k_gemm64<<<gemm_grid, 256, smem64>>>(p_ha, p_w2, p_t);
    k_agg_fc<<<agg_grid, 256>>>((const __half2*)p_t, b2, fw, fb, out);
}

// round 7
// speedup vs baseline: 1.7304x; 1.0406x over previous
#include <cuda_runtime.h>
#include <cuda_fp16.h>
#include <math.h>
#include <stdint.h>

#define NN 50000
#define EE 800000
#define DIN 128
#define DH 64
#define DOUT 16
#define NCHUNK ((NN + 255) / 256)   // 196
#define EBLK ((EE + 255) / 256)     // 3125

// Scratch (device globals; no allocation allowed)
__device__ __align__(256) __half g_th[NN * DH];      // GEMM out / agg in
__device__ __align__(256) __half g_ha[NN * DH];      // agg out / GEMM in
__device__ float g_dinv[NN];
__device__ int g_cnt[NN];
__device__ int g_lexcl[NN];
__device__ int g_rowptr[NN + 1];
__device__ int g_loc[EE];
__device__ int g_col[EE];
__device__ int g_chtot[256];

// ---------------------------------------------------------------- preprocessing
__global__ void k_count(const int* __restrict__ dst) {
    int i = blockIdx.x * blockDim.x + threadIdx.x;
    if (i < EE) g_loc[i] = atomicAdd(&g_cnt[dst[i]], 1);
}

__global__ void k_scan1() {
    __shared__ int wsum[8];
    int tid = threadIdx.x;
    int i = blockIdx.x * 256 + tid;
    int v = (i < NN) ? g_cnt[i] : 0;
    if (i < NN) g_dinv[i] = rsqrtf((float)(v + 1));
    int lane = tid & 31, w = tid >> 5;
    int incl = v;
#pragma unroll
    for (int o = 1; o < 32; o <<= 1) {
        int t = __shfl_up_sync(0xffffffffu, incl, o);
        if (lane >= o) incl += t;
    }
    if (lane == 31) wsum[w] = incl;
    __syncthreads();
    if (w == 0) {
        int s = (lane < 8) ? wsum[lane] : 0;
#pragma unroll
        for (int o = 1; o < 8; o <<= 1) {
            int t = __shfl_up_sync(0xffffffffu, s, o);
            if (lane >= o) s += t;
        }
        if (lane < 8) wsum[lane] = s;
    }
    __syncthreads();
    int woff = (w > 0) ? wsum[w - 1] : 0;
    if (i < NN) g_lexcl[i] = woff + incl - v;
    if (tid == 255) g_chtot[blockIdx.x] = woff + incl;
}

__global__ void k_finish(const int* __restrict__ src, const int* __restrict__ dst) {
    __shared__ int soff[256];
    __shared__ int wsum[8];
    int tid = threadIdx.x;
    {
        int v = (tid < NCHUNK) ? g_chtot[tid] : 0;
        int lane = tid & 31, w = tid >> 5;
        int incl = v;
#pragma unroll
        for (int o = 1; o < 32; o <<= 1) {
            int t = __shfl_up_sync(0xffffffffu, incl, o);
            if (lane >= o) incl += t;
        }
        if (lane == 31) wsum[w] = incl;
        __syncthreads();
        if (w == 0) {
            int s = (lane < 8) ? wsum[lane] : 0;
#pragma unroll
            for (int o = 1; o < 8; o <<= 1) {
                int t = __shfl_up_sync(0xffffffffu, s, o);
                if (lane >= o) s += t;
            }
            if (lane < 8) wsum[lane] = s;
        }
        __syncthreads();
        int woff = (w > 0) ? wsum[w - 1] : 0;
        soff[tid] = woff + incl - v;
        __syncthreads();
    }
    int b = blockIdx.x;
    if (b < NCHUNK) {
        int i = b * 256 + tid;
        if (i < NN) g_rowptr[i] = g_lexcl[i] + soff[b];
        if (b == 0 && tid == 0) g_rowptr[NN] = EE;
    } else {
        int i = (b - NCHUNK) * 256 + tid;
        if (i < EE) {
            int d = dst[i];
            g_col[g_lexcl[d] + soff[d >> 8] + g_loc[i]] = src[i];
        }
    }
}

// ---------------------------------------------------------------- tensor-core GEMM
__device__ __forceinline__ void mma16816(float* d, uint32_t a0, uint32_t a1,
                                         uint32_t a2, uint32_t a3, uint32_t b0,
                                         uint32_t b1) {
    asm volatile(
        "mma.sync.aligned.m16n8k16.row.col.f32.f16.f16.f32 "
        "{%0,%1,%2,%3}, {%4,%5,%6,%7}, {%8,%9}, {%0,%1,%2,%3};\n"
        : "+f"(d[0]), "+f"(d[1]), "+f"(d[2]), "+f"(d[3])
        : "r"(a0), "r"(a1), "r"(a2), "r"(a3), "r"(b0), "r"(b1));
}

template <int K, int LDA, int LDB>
__device__ __forceinline__ void gemm_tile_compute(const __half* sA, const __half* sB,
                                                  __half* C, int base) {
    int tid = threadIdx.x;
    int warp = tid >> 5, lane = tid & 31;
    int grp = lane >> 2, tig = lane & 3;
    int rowA = warp * 16 + grp;
    float acc[8][4];
#pragma unroll
    for (int j = 0; j < 8; j++)
#pragma unroll
        for (int q = 0; q < 4; q++) acc[j][q] = 0.f;

#pragma unroll
    for (int kc = 0; kc < K; kc += 16) {
        uint32_t a0 = *(const uint32_t*)(sA + rowA * LDA + kc + 2 * tig);
        uint32_t a1 = *(const uint32_t*)(sA + (rowA + 8) * LDA + kc + 2 * tig);
        uint32_t a2 = *(const uint32_t*)(sA + rowA * LDA + kc + 2 * tig + 8);
        uint32_t a3 = *(const uint32_t*)(sA + (rowA + 8) * LDA + kc + 2 * tig + 8);
#pragma unroll
        for (int j = 0; j < 8; j++) {
            uint32_t b0 = *(const uint32_t*)(sB + (j * 8 + grp) * LDB + kc + 2 * tig);
            uint32_t b1 = *(const uint32_t*)(sB + (j * 8 + grp) * LDB + kc + 2 * tig + 8);
            mma16816(acc[j], a0, a1, a2, a3, b0, b1);
        }
    }
    int r0 = base + rowA, r1 = r0 + 8;
#pragma unroll
    for (int j = 0; j < 8; j++) {
        int col = j * 8 + 2 * tig;
        if (r0 < NN)
            *(__half2*)(C + (size_t)r0 * DH + col) = __floats2half2_rn(acc[j][0], acc[j][1]);
        if (r1 < NN)
            *(__half2*)(C + (size_t)r1 * DH + col) = __floats2half2_rn(acc[j][2], acc[j][3]);
    }
}

// GEMM0: fp32 x and fp32 W0 read directly, converted during smem stage
__global__ void k_gemm0(const float* __restrict__ A, const float* __restrict__ W,
                        __half* __restrict__ C) {
    constexpr int K = DIN, LDA = K + 8, LDB = K + 8;
    extern __shared__ __half sm[];
    __half* sA = sm;
    __half* sB = sm + 128 * LDA;
    int tid = threadIdx.x;
    int base = blockIdx.x * 128;

    for (int i = tid; i < K * 64; i += 256) {
        int k = i >> 6, n = i & 63;
        sB[n * LDB + k] = __float2half_rn(W[i]);
    }
    for (int i = tid; i < 128 * (K / 4); i += 256) {
        int r = i / (K / 4), c = i % (K / 4);
        float4 v = make_float4(0.f, 0.f, 0.f, 0.f);
        if (base + r < NN) v = *(const float4*)(A + (size_t)(base + r) * K + c * 4);
        __half2* p = (__half2*)(sA + r * LDA + c * 4);
        p[0] = __floats2half2_rn(v.x, v.y);
        p[1] = __floats2half2_rn(v.z, v.w);
    }
    __syncthreads();
    gemm_tile_compute<K, LDA, LDB>(sA, sB, C, base);
}

// GEMM 1/2: fp16 A, fp32 W converted during smem stage
__global__ void k_gemm64(const __half* __restrict__ A, const float* __restrict__ W,
                         __half* __restrict__ C) {
    constexpr int K = DH, LDA = K + 8, LDB = K + 8;
    extern __shared__ __half sm[];
    __half* sA = sm;
    __half* sB = sm + 128 * LDA;
    int tid = threadIdx.x;
    int base = blockIdx.x * 128;

    for (int i = tid; i < K * 64; i += 256) {
        int k = i >> 6, n = i & 63;
        sB[n * LDB + k] = __float2half_rn(W[i]);
    }
    for (int i = tid; i < 128 * (K / 8); i += 256) {
        int r = i / (K / 8), c = i % (K / 8);
        uint4 v = make_uint4(0u, 0u, 0u, 0u);
        if (base + r < NN) v = *(const uint4*)(A + (size_t)(base + r) * K + c * 8);
        *(uint4*)(sA + r * LDA + c * 8) = v;
    }
    __syncthreads();
    gemm_tile_compute<K, LDA, LDB>(sA, sB, C, base);
}

// ------------------------------------------------------- aggregation body
__device__ __forceinline__ float2 agg_node(const __half2* __restrict__ hin, int node,
                                           int lane, float2 bb) {
    float dd = g_dinv[node];
    int beg = g_rowptr[node], end = g_rowptr[node + 1];
    float2 hv = __half22float2(hin[(size_t)node * 32 + lane]);
    float2 acc = make_float2(hv.x * dd * dd, hv.y * dd * dd);
    int k = beg;
    for (; k + 4 <= end; k += 4) {
        int j0 = g_col[k], j1 = g_col[k + 1], j2 = g_col[k + 2], j3 = g_col[k + 3];
        float n0 = g_dinv[j0] * dd, n1 = g_dinv[j1] * dd;
        float n2 = g_dinv[j2] * dd, n3 = g_dinv[j3] * dd;
        float2 h0 = __half22float2(hin[(size_t)j0 * 32 + lane]);
        float2 h1 = __half22float2(hin[(size_t)j1 * 32 + lane]);
        float2 h2 = __half22float2(hin[(size_t)j2 * 32 + lane]);
        float2 h3 = __half22float2(hin[(size_t)j3 * 32 + lane]);
        acc.x = fmaf(h0.x, n0, acc.x); acc.y = fmaf(h0.y, n0, acc.y);
        acc.x = fmaf(h1.x, n1, acc.x); acc.y = fmaf(h1.y, n1, acc.y);
        acc.x = fmaf(h2.x, n2, acc.x); acc.y = fmaf(h2.y, n2, acc.y);
        acc.x = fmaf(h3.x, n3, acc.x); acc.y = fmaf(h3.y, n3, acc.y);
    }
    for (; k < end; k++) {
        int j = g_col[k];
        float n = g_dinv[j] * dd;
        float2 h = __half22float2(hin[(size_t)j * 32 + lane]);
        acc.x = fmaf(h.x, n, acc.x);
        acc.y = fmaf(h.y, n, acc.y);
    }
    acc.x += bb.x;
    acc.y += bb.y;
    acc.x = (acc.x > 0.f) ? acc.x : expm1f(acc.x);
    acc.y = (acc.y > 0.f) ? acc.y : expm1f(acc.y);
    return acc;
}

__global__ void k_agg(const __half2* __restrict__ hin, __half2* __restrict__ hout,
                      const float* __restrict__ bias) {
    int lane = threadIdx.x;
    int node = blockIdx.x * 8 + threadIdx.y;
    if (node >= NN) return;
    float2 bb = ((const float2*)bias)[lane];
    float2 acc = agg_node(hin, node, lane, bb);
    hout[(size_t)node * 32 + lane] = __floats2half2_rn(acc.x, acc.y);
}

// last aggregation + FC + softmax fused (layer 2)
__global__ void k_agg_fc(const __half2* __restrict__ hin, const float* __restrict__ bias,
                         const float* __restrict__ fw, const float* __restrict__ fb,
                         float* __restrict__ out) {
    __shared__ float sW[DH * DOUT];
    __shared__ float sh[8][DH];
    for (int i = threadIdx.x; i < DH * DOUT; i += 256) sW[i] = fw[i];
    __syncthreads();
    int warp = threadIdx.x >> 5, lane = threadIdx.x & 31;
    int node = blockIdx.x * 8 + warp;
    if (node >= NN) return;
    float2 bb = ((const float2*)bias)[lane];
    float2 acc = agg_node(hin, node, lane, bb);
    sh[warp][2 * lane] = acc.x;
    sh[warp][2 * lane + 1] = acc.y;
    __syncwarp();
    float v = 0.f;
    if (lane < DOUT) {
        v = fb[lane];
#pragma unroll
        for (int kk = 0; kk < DH; kk++) v = fmaf(sh[warp][kk], sW[kk * DOUT + lane], v);
    }
    float m = v;
#pragma unroll
    for (int o = 8; o; o >>= 1) m = fmaxf(m, __shfl_xor_sync(0xffffffffu, m, o, 16));
    float e = (lane < DOUT) ? expf(v - m) : 0.f;
    float s = e;
#pragma unroll
    for (int o = 8; o; o >>= 1) s += __shfl_xor_sync(0xffffffffu, s, o, 16);
    if (lane < DOUT) out[(size_t)node * DOUT + lane] = e / s;
}

// ---------------------------------------------------------------- launch
extern "C" void kernel_launch(void* const* d_in, const int* in_sizes, int n_in,
                              void* d_out, int out_size) {
    const float* x = (const float*)d_in[0];
    const int* ei = (const int*)d_in[1];
    const float* w0 = (const float*)d_in[2];
    const float* b0 = (const float*)d_in[3];
    const float* w1 = (const float*)d_in[4];
    const float* b1 = (const float*)d_in[5];
    const float* w2 = (const float*)d_in[6];
    const float* b2 = (const float*)d_in[7];
    const float* fw = (const float*)d_in[8];
    const float* fb = (const float*)d_in[9];
    float* out = (float*)d_out;
    const int* src = ei;
    const int* dst = ei + EE;

    __half *p_t, *p_ha;
    int* p_cnt;
    cudaGetSymbolAddress((void**)&p_t, g_th);
    cudaGetSymbolAddress((void**)&p_ha, g_ha);
    cudaGetSymbolAddress((void**)&p_cnt, g_cnt);

    const int smem128 = (128 * (DIN + 8) + 64 * (DIN + 8)) * 2;  // 52224 B
    const int smem64 = (128 * (DH + 8) + 64 * (DH + 8)) * 2;     // 27648 B

    // one-time host-side resource setup (uncaptured first call)
    static cudaStream_t s2 = nullptr;
    static cudaEvent_t evFork = nullptr, evJoin = nullptr;
    if (!s2) {
        cudaStreamCreateWithFlags(&s2, cudaStreamNonBlocking);
        cudaEventCreateWithFlags(&evFork, cudaEventDisableTiming);
        cudaEventCreateWithFlags(&evJoin, cudaEventDisableTiming);
        cudaFuncSetAttribute(k_gemm0, cudaFuncAttributeMaxDynamicSharedMemorySize, smem128);
        cudaFuncSetAttribute(k_gemm64, cudaFuncAttributeMaxDynamicSharedMemorySize, smem64);
    }

    const int gemm_grid = (NN + 127) / 128;
    const dim3 agg_block(32, 8);
    const int agg_grid = (NN + 7) / 8;

    // fork: edge-preprocessing chain on s2, GEMM0 on main stream
    cudaEventRecord(evFork, 0);
    cudaStreamWaitEvent(s2, evFork, 0);
    cudaMemsetAsync(p_cnt, 0, NN * sizeof(int), s2);
    k_count<<<EBLK, 256, 0, s2>>>(dst);
    k_scan1<<<NCHUNK, 256, 0, s2>>>();
    k_finish<<<NCHUNK + EBLK, 256, 0, s2>>>(src, dst);
    cudaEventRecord(evJoin, s2);

    k_gemm0<<<gemm_grid, 256, smem128>>>(x, w0, p_t);

    // join: aggregation needs both CSR and GEMM0 output
    cudaStreamWaitEvent(0, evJoin, 0);

    k_agg<<<agg_grid, agg_block>>>((const __half2*)p_t, (__half2*)p_ha, b0);
    k_gemm64<<<gemm_grid, 256, smem64>>>(p_ha, w1, p_t);
    k_agg<<<agg_grid, agg_block>>>((const __half2*)p_t, (__half2*)p_ha, b1);
    k_gemm64<<<gemm_grid, 256, smem64>>>(p_ha, w2, p_t);
    k_agg_fc<<<agg_grid, 256>>>((const __half2*)p_t, b2, fw, fb, out);
}